// round 11
// baseline (speedup 1.0000x reference)
#include <cuda_runtime.h>
#include <cuda_fp16.h>
#include <cstdint>

#define DINLINE __device__ __forceinline__

static constexpr int MAXN = 2048;
static constexpr int FIN  = 128;

// ---- scratch (device globals; no allocation allowed) ----
__device__ __align__(16) float g_Cs[MAXN * 1024];   // spline GEMM out [n][1024]
__device__ unsigned char g_cfl[MAXN * FIN];         // [n][i]
__device__ unsigned g_arrive = 0, g_done = 0;       // grid barrier state (self-resetting)

// ---------------- PTX helpers ----------------
DINLINE uint32_t smem_u32(const void* p) {
    uint32_t a;
    asm("{ .reg .u64 t; cvta.to.shared.u64 t, %1; cvt.u32.u64 %0, t; }" : "=r"(a) : "l"(p));
    return a;
}
DINLINE void sts128(uint32_t addr, uint4 v) {
    asm volatile("st.shared.v4.b32 [%0], {%1,%2,%3,%4};"
                 :: "r"(addr), "r"(v.x), "r"(v.y), "r"(v.z), "r"(v.w));
}
DINLINE void ldsm_x4(uint32_t& r0, uint32_t& r1, uint32_t& r2, uint32_t& r3, uint32_t addr) {
    asm volatile("ldmatrix.sync.aligned.m8n8.x4.shared.b16 {%0,%1,%2,%3}, [%4];"
                 : "=r"(r0), "=r"(r1), "=r"(r2), "=r"(r3) : "r"(addr));
}
DINLINE void ldsm_x4_t(uint32_t& r0, uint32_t& r1, uint32_t& r2, uint32_t& r3, uint32_t addr) {
    asm volatile("ldmatrix.sync.aligned.m8n8.x4.trans.shared.b16 {%0,%1,%2,%3}, [%4];"
                 : "=r"(r0), "=r"(r1), "=r"(r2), "=r"(r3) : "r"(addr));
}
DINLINE void mma16816(float* d, const uint32_t* a, const uint32_t* b) {
    asm volatile(
        "mma.sync.aligned.m16n8k16.row.col.f32.f16.f16.f32 "
        "{%0,%1,%2,%3}, {%4,%5,%6,%7}, {%8,%9}, {%0,%1,%2,%3};"
        : "+f"(d[0]), "+f"(d[1]), "+f"(d[2]), "+f"(d[3])
        : "r"(a[0]), "r"(a[1]), "r"(a[2]), "r"(a[3]), "r"(b[0]), "r"(b[1]));
}
DINLINE uint32_t pack_h2(float a, float b) {
    uint32_t r;
    asm("cvt.rn.f16x2.f32 %0, %1, %2;" : "=r"(r) : "f"(b), "f"(a));
    return r;
}
DINLINE uint32_t swz(int row, int q) {   // 256B rows, 16-byte chunks q=0..15
    return (uint32_t)(row * 256 + (((q & 8) | ((q ^ row) & 7)) * 16));
}

static constexpr uint32_t WOFF = 32768;

// ---- templated mainloop over B layout (non-trans: n-major; trans: k-major) ----
template <bool TB>
DINLINE void gemm_main(uint32_t sb, int lane, int wm, int wn, float (&acc)[4][4][4]) {
    const int a_lrow = wm * 64 + (lane & 15);
    const int a_lsel = lane >> 4;
    const int b_lrow0 = wn * 32 + ((lane >> 4) << 3) + (lane & 7);   // non-trans
    const int b_lsel = (lane >> 3) & 1;
    const int bt_row = (lane & 7) + 8 * ((lane >> 3) & 1);           // trans
    const int bt_q0  = wn * 4 + (lane >> 4);
#pragma unroll
    for (int ks = 0; ks < 8; ++ks) {
        uint32_t af[4][4];
#pragma unroll
        for (int mt = 0; mt < 4; ++mt) {
            int row = a_lrow + mt * 16;
            ldsm_x4(af[mt][0], af[mt][1], af[mt][2], af[mt][3],
                    sb + swz(row, ks * 2 + a_lsel));
        }
        uint32_t bf[4][2];
#pragma unroll
        for (int h = 0; h < 2; ++h) {
            uint32_t r0, r1, r2, r3;
            if (!TB) {
                int row = b_lrow0 + h * 16;
                ldsm_x4(r0, r1, r2, r3, sb + WOFF + swz(row, ks * 2 + b_lsel));
            } else {
                int row = ks * 16 + bt_row;
                ldsm_x4_t(r0, r1, r2, r3, sb + WOFF + swz(row, bt_q0 + h * 2));
            }
            bf[h * 2][0] = r0;     bf[h * 2][1] = r1;
            bf[h * 2 + 1][0] = r2; bf[h * 2 + 1][1] = r3;
        }
#pragma unroll
        for (int mt = 0; mt < 4; ++mt)
#pragma unroll
            for (int nt = 0; nt < 4; ++nt)
                mma16816(acc[mt][nt], af[mt], bf[nt]);
    }
}

// ---- THE kernel: stage W + act A -> HMMA -> epilogue -> grid barrier -> finalize ----
__global__ void __launch_bounds__(256) k_fused(const float* __restrict__ x,
                                               const float* __restrict__ bw,
                                               const float* __restrict__ sw,
                                               float* __restrict__ out, int N) {
    extern __shared__ __align__(128) char smem[];
    const uint32_t sb = smem_u32(smem);
    const int tid = threadIdx.x, lane = tid & 31, wid = tid >> 5;
    const int m0 = blockIdx.x * 128, ct = blockIdx.y;
    const int sel = (ct == 0) ? 0 : 1 + ((ct - 1) >> 1);
    const int row = tid >> 1, half = tid & 1;

    // ---- stage W tile (coalesced in gmem either way; same smem addressing) ----
    const float* wsrc = (ct == 0) ? (bw + row * 128 + half * 64)             // n-major rows (c)
                                  : (sw + row * 1024 + (ct - 1) * 128 + half * 64); // k-major rows (k)
#pragma unroll
    for (int cc = 0; cc < 8; ++cc) {
        float4 w0 = *(const float4*)(wsrc + cc * 8);
        float4 w1 = *(const float4*)(wsrc + cc * 8 + 4);
        uint4 hv;
        hv.x = pack_h2(w0.x, w0.y);
        hv.y = pack_h2(w0.z, w0.w);
        hv.z = pack_h2(w1.x, w1.y);
        hv.w = pack_h2(w1.z, w1.w);
        sts128(sb + WOFF + swz(row, half * 8 + cc), hv);
    }

    // ---- stage A tile: activation -> fp16 swizzled smem ----
    const float* xr = x + (m0 + row) * 128 + half * 64;
    const float s6 = 0.16666666666666666f;
#pragma unroll
    for (int cc = 0; cc < 8; ++cc) {
        float4 a0 = *(const float4*)(xr + cc * 8);
        float4 a1 = *(const float4*)(xr + cc * 8 + 4);
        float xv[8] = {a0.x, a0.y, a0.z, a0.w, a1.x, a1.y, a1.z, a1.w};
        float v[8];
        uint32_t cfb[8];
#pragma unroll
        for (int e = 0; e < 8; ++e) {
            float xe = xv[e];
            if (sel == 0) {
                v[e] = xe / (1.0f + __expf(-xe));
            } else {
                float xn = fminf(fmaxf(xe, -1.0f), 1.0f);
                float tt = (xn + 2.2f) * 2.5f;
                float fl = floorf(tt);
                float u  = tt - fl;
                int ii = (int)fl; ii = ii < 3 ? 3 : (ii > 7 ? 7 : ii);
                float u2 = u * u;
                if (sel == 1) v[e] = s6 * (1.0f + u * (-3.0f + u * (3.0f - u)));
                if (sel == 2) v[e] = s6 * (4.0f + u2 * (3.0f * u - 6.0f));
                if (sel == 3) v[e] = s6 * (1.0f + u * (3.0f + u * (3.0f - 3.0f * u)));
                if (sel == 4) v[e] = s6 * (u2 * u);
                cfb[e] = (uint32_t)(ii - 3);
            }
        }
        uint4 hv;
        hv.x = pack_h2(v[0], v[1]);
        hv.y = pack_h2(v[2], v[3]);
        hv.z = pack_h2(v[4], v[5]);
        hv.w = pack_h2(v[6], v[7]);
        sts128(sb + swz(row, half * 8 + cc), hv);
        if (ct == 1) {
            uint2 cw;
            cw.x = cfb[0] | (cfb[1] << 8) | (cfb[2] << 16) | (cfb[3] << 24);
            cw.y = cfb[4] | (cfb[5] << 8) | (cfb[6] << 16) | (cfb[7] << 24);
            *(uint2*)(g_cfl + (m0 + row) * 128 + half * 64 + cc * 8) = cw;
        }
    }
    __syncthreads();

    // ---- mainloop ----
    const int wm = wid >> 2, wn = wid & 3;   // warp tile 64x32
    float acc[4][4][4];
#pragma unroll
    for (int i = 0; i < 4; ++i)
#pragma unroll
        for (int j = 0; j < 4; ++j)
#pragma unroll
            for (int k = 0; k < 4; ++k) acc[i][j][k] = 0.0f;

    if (ct == 0) gemm_main<false>(sb, lane, wm, wn, acc);
    else         gemm_main<true >(sb, lane, wm, wn, acc);

    // ---- epilogue ----
    const int er = lane >> 2, ec = (lane & 3) * 2;
    if (ct == 0) {
#pragma unroll
        for (int mt = 0; mt < 4; ++mt)
#pragma unroll
            for (int nt = 0; nt < 4; ++nt) {
                int r = m0 + wm * 64 + mt * 16 + er;
                int c = wn * 32 + nt * 8 + ec;
                *(float2*)&out[r * 128 + c]       = make_float2(acc[mt][nt][0], acc[mt][nt][1]);
                *(float2*)&out[(r + 8) * 128 + c] = make_float2(acc[mt][nt][2], acc[mt][nt][3]);
            }
    } else {
#pragma unroll
        for (int mt = 0; mt < 4; ++mt)
#pragma unroll
            for (int nt = 0; nt < 4; ++nt) {
                int r = m0 + wm * 64 + mt * 16 + er;
                int c = (ct - 1) * 128 + wn * 32 + nt * 8 + ec;
                *(float2*)&g_Cs[r * 1024 + c]       = make_float2(acc[mt][nt][0], acc[mt][nt][1]);
                *(float2*)&g_Cs[(r + 8) * 1024 + c] = make_float2(acc[mt][nt][2], acc[mt][nt][3]);
            }
    }

    // ---- grid barrier (all 144 CTAs co-resident: 144 <= 148 SMs) ----
    const unsigned NCTA = gridDim.x * gridDim.y;
    __syncthreads();
    if (tid == 0) {
        __threadfence();
        atomicAdd(&g_arrive, 1u);
        while (atomicAdd(&g_arrive, 0u) < NCTA) {}
        __threadfence();
    }
    __syncthreads();

    // ---- distributed finalize: out[n,o] += sum_jp Cs[n, jp*256 + q*8 + cfl[n, jp*32+q] + r2] ----
    const int total = N * 128;
    const int gstride = (int)NCTA * 256;
    for (int idx = (blockIdx.y * gridDim.x + blockIdx.x) * 256 + tid; idx < total; idx += gstride) {
        int n = idx >> 7, o = idx & 127;
        int q = o >> 2, r2 = o & 3;
        float accv = out[idx];
        const unsigned char* cf = g_cfl + n * 128;
        const float* Cs = g_Cs + n * 1024 + q * 8 + r2;
        float t0 = Cs[cf[q]];
        float t1 = Cs[256 + cf[32 + q]];
        float t2 = Cs[512 + cf[64 + q]];
        float t3 = Cs[768 + cf[96 + q]];
        out[idx] = accv + (t0 + t1) + (t2 + t3);
    }

    // ---- reset barrier state for next (graph-replayed) launch ----
    __syncthreads();
    if (tid == 0) {
        unsigned d = atomicAdd(&g_done, 1u);
        if (d == NCTA - 1u) {
            g_arrive = 0;
            g_done = 0;
            __threadfence();
        }
    }
}

extern "C" void kernel_launch(void* const* d_in, const int* in_sizes, int n_in,
                              void* d_out, int out_size) {
    const float* x  = (const float*)d_in[0];
    const float* bw = (const float*)d_in[1];
    const float* sw = (const float*)d_in[2];
    float* out = (float*)d_out;
    int N = in_sizes[0] / FIN;
    if (N > MAXN) N = MAXN;

    const int smem = 32768 + 32768;  // 64 KB
    cudaFuncSetAttribute(k_fused, cudaFuncAttributeMaxDynamicSharedMemorySize, smem);

    dim3 grid(N / 128, 9);           // 144 CTAs for N=2048 — one co-resident wave
    k_fused<<<grid, 256, smem>>>(x, bw, sw, out, N);
}

// round 12
// speedup vs baseline: 1.4660x; 1.4660x over previous
#include <cuda_runtime.h>
#include <cuda_fp16.h>
#include <cstdint>

#define DINLINE __device__ __forceinline__

static constexpr int MAXN = 2048;
static constexpr int FIN  = 128;

// ---- scratch (device globals; no allocation allowed) ----
__device__ __align__(16) __half g_Ah[5][MAXN][128];   // [sel][n][i] fp16
__device__ __align__(16) __half g_Wh[1152][128];      // [c][k] fp16, N-major
__device__ __align__(16) float g_Cs[MAXN * 1024];     // spline GEMM out [n][1024]
__device__ unsigned char g_cflp[MAXN * FIN];          // planar [n][jp][q]
__device__ unsigned g_cnt[16] = {};                   // per-m-block arrival counters
__device__ unsigned g_cnt2[16] = {};                  // per-m-block done counters

// ---------------- PTX helpers ----------------
DINLINE uint32_t smem_u32(const void* p) {
    uint32_t a;
    asm("{ .reg .u64 t; cvta.to.shared.u64 t, %1; cvt.u32.u64 %0, t; }" : "=r"(a) : "l"(p));
    return a;
}
DINLINE void cp16(uint32_t s, const void* g) {
    asm volatile("cp.async.cg.shared.global [%0], [%1], 16;" :: "r"(s), "l"(g));
}
DINLINE void cp_commit() { asm volatile("cp.async.commit_group;"); }
template <int N_> DINLINE void cp_wait() {
    asm volatile("cp.async.wait_group %0;" :: "n"(N_));
}
DINLINE void ldsm_x4(uint32_t& r0, uint32_t& r1, uint32_t& r2, uint32_t& r3, uint32_t addr) {
    asm volatile("ldmatrix.sync.aligned.m8n8.x4.shared.b16 {%0,%1,%2,%3}, [%4];"
                 : "=r"(r0), "=r"(r1), "=r"(r2), "=r"(r3) : "r"(addr));
}
DINLINE void mma16816(float* d, const uint32_t* a, const uint32_t* b) {
    asm volatile(
        "mma.sync.aligned.m16n8k16.row.col.f32.f16.f16.f32 "
        "{%0,%1,%2,%3}, {%4,%5,%6,%7}, {%8,%9}, {%0,%1,%2,%3};"
        : "+f"(d[0]), "+f"(d[1]), "+f"(d[2]), "+f"(d[3])
        : "r"(a[0]), "r"(a[1]), "r"(a[2]), "r"(a[3]), "r"(b[0]), "r"(b[1]));
}
DINLINE uint32_t pack_h2(float a, float b) {
    uint32_t r;
    asm("cvt.rn.f16x2.f32 %0, %1, %2;" : "=r"(r) : "f"(b), "f"(a));
    return r;
}

// ---- K1: all prep (R10, proven). Grid: [0,PA4) act; [PA4,PA4+8) baseW; then 128 splineW ----
__global__ void __launch_bounds__(256) k_prep(const float* __restrict__ x,
                                              const float* __restrict__ bw,
                                              const float* __restrict__ sw,
                                              int PA4) {
    __shared__ float tile[32][33];
    const int b = blockIdx.x, t = threadIdx.x;
    if (b < PA4) {
        int idx4 = b * 256 + t;
        int n = idx4 >> 5, c4 = idx4 & 31;
        float4 x0 = *(const float4*)(x + n * 128 + c4 * 4);
        float xv[4] = {x0.x, x0.y, x0.z, x0.w};
        float v[5][4];
        uint32_t cfb[4];
        const float s6 = 0.16666666666666666f;
#pragma unroll
        for (int e = 0; e < 4; ++e) {
            float xe = xv[e];
            v[0][e] = xe / (1.0f + __expf(-xe));
            float xn = fminf(fmaxf(xe, -1.0f), 1.0f);
            float tt = (xn + 2.2f) * 2.5f;
            float fl = floorf(tt);
            float u  = tt - fl;
            int ii = (int)fl; ii = ii < 3 ? 3 : (ii > 7 ? 7 : ii);
            float u2 = u * u;
            v[1][e] = s6 * (1.0f + u * (-3.0f + u * (3.0f - u)));
            v[2][e] = s6 * (4.0f + u2 * (3.0f * u - 6.0f));
            v[3][e] = s6 * (1.0f + u * (3.0f + u * (3.0f - 3.0f * u)));
            v[4][e] = s6 * (u2 * u);
            cfb[e] = (uint32_t)(ii - 3);
        }
#pragma unroll
        for (int s = 0; s < 5; ++s) {
            uint2 hv;
            hv.x = pack_h2(v[s][0], v[s][1]);
            hv.y = pack_h2(v[s][2], v[s][3]);
            *(uint2*)&g_Ah[s][n][c4 * 4] = hv;
        }
        uint32_t cw = cfb[0] | (cfb[1] << 8) | (cfb[2] << 16) | (cfb[3] << 24);
        *(uint32_t*)(g_cflp + n * 128 + (c4 >> 3) * 32 + (c4 & 7) * 4) = cw;
    } else if (b < PA4 + 8) {
        int f8 = (b - PA4) * 256 + t;
        int c = f8 >> 4, ch = f8 & 15;
        const float4* wp = (const float4*)(bw + c * 128 + ch * 8);
        float4 w0 = wp[0], w1 = wp[1];
        uint4 hv;
        hv.x = pack_h2(w0.x, w0.y);
        hv.y = pack_h2(w0.z, w0.w);
        hv.z = pack_h2(w1.x, w1.y);
        hv.w = pack_h2(w1.z, w1.w);
        *(uint4*)&g_Wh[c][ch * 8] = hv;
    } else {
        int bb = b - PA4 - 8;
        int bc = bb >> 2, bi = bb & 3;
        int tx = t & 31, ty = t >> 5;
#pragma unroll
        for (int iy = 0; iy < 4; ++iy) {
            int il = ty + 8 * iy;
            tile[il][tx] = sw[(bi * 32 + il) * 1024 + bc * 32 + tx];
        }
        __syncthreads();
        {
            int cl = t >> 3, ch = t & 7;
            uint2 hv;
            hv.x = pack_h2(tile[ch * 4 + 0][cl], tile[ch * 4 + 1][cl]);
            hv.y = pack_h2(tile[ch * 4 + 2][cl], tile[ch * 4 + 3][cl]);
            int c = 128 + bc * 32 + cl, i = bi * 32 + ch * 4;
            *(uint2*)&g_Wh[c][i] = hv;
        }
    }
}

// ---- K2: fp16 HMMA GEMM + fused finalize. grid (M/128, 9), 256 thr ----
DINLINE void gemm_pass(uint32_t sb, int ks0, int ks1,
                       int a_lrow, int a_lsel, int b_lrow0, int b_lsel,
                       float (&acc)[4][4][4]) {
#pragma unroll
    for (int ks = ks0; ks < ks1; ++ks) {
        uint32_t af[4][4];
#pragma unroll
        for (int mt = 0; mt < 4; ++mt) {
            int row = a_lrow + mt * 16;
            int q = ks * 2 + a_lsel;
            uint32_t addr = sb + row * 256 + (((q & 8) | ((q ^ row) & 7)) * 16);
            ldsm_x4(af[mt][0], af[mt][1], af[mt][2], af[mt][3], addr);
        }
        uint32_t bf[4][2];
#pragma unroll
        for (int h = 0; h < 2; ++h) {
            int row = b_lrow0 + h * 16;
            int q = ks * 2 + b_lsel;
            uint32_t addr = sb + 32768 + row * 256 + (((q & 8) | ((q ^ row) & 7)) * 16);
            uint32_t r0, r1, r2, r3;
            ldsm_x4(r0, r1, r2, r3, addr);
            bf[h * 2][0] = r0;     bf[h * 2][1] = r1;
            bf[h * 2 + 1][0] = r2; bf[h * 2 + 1][1] = r3;
        }
#pragma unroll
        for (int mt = 0; mt < 4; ++mt)
#pragma unroll
            for (int nt = 0; nt < 4; ++nt)
                mma16816(acc[mt][nt], af[mt], bf[nt]);
    }
}

__global__ void __launch_bounds__(256) k_gemm_mma(float* __restrict__ out) {
    extern __shared__ __align__(128) char smem[];
    const uint32_t sb = smem_u32(smem);
    const int tid = threadIdx.x, lane = tid & 31, wid = tid >> 5;
    const int m0 = blockIdx.x * 128, ct = blockIdx.y;
    const int sel = (ct == 0) ? 0 : 1 + ((ct - 1) >> 1);

    const __half* Asrc = &g_Ah[sel][m0][0];
#pragma unroll
    for (int it = 0; it < 4; ++it) {
        int idx = it * 256 + tid;
        int row = idx >> 3, q = idx & 7;
        cp16(sb + row * 256 + (((q & 8) | ((q ^ row) & 7)) * 16), Asrc + row * 128 + q * 8);
    }
#pragma unroll
    for (int it = 0; it < 4; ++it) {
        int idx = it * 256 + tid;
        int row = idx >> 3, q = idx & 7;
        cp16(sb + 32768 + row * 256 + (((q & 8) | ((q ^ row) & 7)) * 16),
             &g_Wh[ct * 128 + row][q * 8]);
    }
    cp_commit();
#pragma unroll
    for (int it = 0; it < 4; ++it) {
        int idx = it * 256 + tid;
        int row = idx >> 3, q = 8 + (idx & 7);
        cp16(sb + row * 256 + (((q & 8) | ((q ^ row) & 7)) * 16), Asrc + row * 128 + q * 8);
    }
#pragma unroll
    for (int it = 0; it < 4; ++it) {
        int idx = it * 256 + tid;
        int row = idx >> 3, q = 8 + (idx & 7);
        cp16(sb + 32768 + row * 256 + (((q & 8) | ((q ^ row) & 7)) * 16),
             &g_Wh[ct * 128 + row][q * 8]);
    }
    cp_commit();

    const int wm = wid >> 2, wn = wid & 3;
    float acc[4][4][4];
#pragma unroll
    for (int i = 0; i < 4; ++i)
#pragma unroll
        for (int j = 0; j < 4; ++j)
#pragma unroll
            for (int k = 0; k < 4; ++k) acc[i][j][k] = 0.0f;

    const int a_lrow = wm * 64 + (lane & 15);
    const int a_lsel = lane >> 4;
    const int b_lrow0 = wn * 32 + ((lane >> 4) << 3) + (lane & 7);
    const int b_lsel = (lane >> 3) & 1;

    cp_wait<1>();
    __syncthreads();
    gemm_pass(sb, 0, 4, a_lrow, a_lsel, b_lrow0, b_lsel, acc);   // k 0..63
    cp_wait<0>();
    __syncthreads();
    gemm_pass(sb, 4, 8, a_lrow, a_lsel, b_lrow0, b_lsel, acc);   // k 64..127

    const int er = lane >> 2, ec = (lane & 3) * 2;
    if (ct == 0) {
#pragma unroll
        for (int mt = 0; mt < 4; ++mt)
#pragma unroll
            for (int nt = 0; nt < 4; ++nt) {
                int row = m0 + wm * 64 + mt * 16 + er;
                int col = wn * 32 + nt * 8 + ec;
                *(float2*)&out[row * 128 + col]       = make_float2(acc[mt][nt][0], acc[mt][nt][1]);
                *(float2*)&out[(row + 8) * 128 + col] = make_float2(acc[mt][nt][2], acc[mt][nt][3]);
            }
    } else {
#pragma unroll
        for (int mt = 0; mt < 4; ++mt)
#pragma unroll
            for (int nt = 0; nt < 4; ++nt) {
                int row = m0 + wm * 64 + mt * 16 + er;
                int col = (ct - 1) * 128 + wn * 32 + nt * 8 + ec;
                *(float2*)&g_Cs[row * 1024 + col]       = make_float2(acc[mt][nt][0], acc[mt][nt][1]);
                *(float2*)&g_Cs[(row + 8) * 1024 + col] = make_float2(acc[mt][nt][2], acc[mt][nt][3]);
            }
    }

    // ---- local 9-CTA sync for this m-block (all co-resident: 144 CTAs <= 148 SMs) ----
    __shared__ unsigned s_old;
    __threadfence();
    __syncthreads();
    if (tid == 0) s_old = atomicAdd(&g_cnt[blockIdx.x], 1u);
    __syncthreads();
    const unsigned old = s_old;
    if (old != 8u) {
        if (tid == 0) {
            while (atomicAdd(&g_cnt[blockIdx.x], 0u) < 9u) { __nanosleep(64); }
        }
        __syncthreads();
    }
    __threadfence();

    // ---- cooperative finalize: 9 CTAs x 256 threads over 16384 outputs of this m-block ----
    const int base = m0 * 128;
#pragma unroll 2
    for (int k = ct * 256 + tid; k < 16384; k += 9 * 256) {
        int idx = base + k;
        int n = idx >> 7, o = k & 127;
        int q = o >> 2, r2 = o & 3;
        float accv = out[idx];
        const unsigned char* cf = g_cflp + n * 128 + q;
        const float* Cs = g_Cs + n * 1024 + q * 8 + r2;
        float t0 = Cs[cf[0]];
        float t1 = Cs[256 + cf[32]];
        float t2 = Cs[512 + cf[64]];
        float t3 = Cs[768 + cf[96]];
        out[idx] = accv + (t0 + t1) + (t2 + t3);
    }

    // ---- done counter; last finisher resets both (graph-replay safe) ----
    __syncthreads();
    if (tid == 0) {
        unsigned d = atomicAdd(&g_cnt2[blockIdx.x], 1u);
        if (d == 8u) {
            g_cnt[blockIdx.x] = 0u;
            g_cnt2[blockIdx.x] = 0u;
            __threadfence();
        }
    }
}

extern "C" void kernel_launch(void* const* d_in, const int* in_sizes, int n_in,
                              void* d_out, int out_size) {
    const float* x  = (const float*)d_in[0];
    const float* bw = (const float*)d_in[1];
    const float* sw = (const float*)d_in[2];
    float* out = (float*)d_out;
    int N = in_sizes[0] / FIN;
    if (N > MAXN) N = MAXN;

    const int smem = 32768 + 32768;  // 64 KB
    cudaFuncSetAttribute(k_gemm_mma, cudaFuncAttributeMaxDynamicSharedMemorySize, smem);

    int PA4 = (N * FIN) / 1024;
    k_prep<<<PA4 + 8 + 128, 256>>>(x, bw, sw, PA4);
    dim3 grid(N / 128, 9);
    k_gemm_mma<<<grid, 256, smem>>>(out);
}

// round 13
// speedup vs baseline: 2.0639x; 1.4079x over previous
#include <cuda_runtime.h>
#include <cuda_fp16.h>
#include <cstdint>

#define DINLINE __device__ __forceinline__

static constexpr int MAXN = 2048;
static constexpr int FIN  = 128;

// ---- scratch (device globals; no allocation allowed) ----
__device__ __align__(16) __half g_Ah[5][MAXN][128];   // [sel][n][i] fp16
__device__ __align__(16) __half g_Wh[1152][128];      // [c][k] fp16, N-major
__device__ __align__(16) float g_Cs[MAXN * 1024];     // spline GEMM out [n][1024]
__device__ unsigned char g_cflp[MAXN * FIN];          // planar [n][jp][q]

// ---------------- PTX helpers ----------------
DINLINE uint32_t smem_u32(const void* p) {
    uint32_t a;
    asm("{ .reg .u64 t; cvta.to.shared.u64 t, %1; cvt.u32.u64 %0, t; }" : "=r"(a) : "l"(p));
    return a;
}
DINLINE void cp16(uint32_t s, const void* g) {
    asm volatile("cp.async.cg.shared.global [%0], [%1], 16;" :: "r"(s), "l"(g));
}
DINLINE void cp_commit() { asm volatile("cp.async.commit_group;"); }
template <int N_> DINLINE void cp_wait() {
    asm volatile("cp.async.wait_group %0;" :: "n"(N_));
}
DINLINE void ldsm_x4(uint32_t& r0, uint32_t& r1, uint32_t& r2, uint32_t& r3, uint32_t addr) {
    asm volatile("ldmatrix.sync.aligned.m8n8.x4.shared.b16 {%0,%1,%2,%3}, [%4];"
                 : "=r"(r0), "=r"(r1), "=r"(r2), "=r"(r3) : "r"(addr));
}
DINLINE void mma16816(float* d, const uint32_t* a, const uint32_t* b) {
    asm volatile(
        "mma.sync.aligned.m16n8k16.row.col.f32.f16.f16.f32 "
        "{%0,%1,%2,%3}, {%4,%5,%6,%7}, {%8,%9}, {%0,%1,%2,%3};"
        : "+f"(d[0]), "+f"(d[1]), "+f"(d[2]), "+f"(d[3])
        : "r"(a[0]), "r"(a[1]), "r"(a[2]), "r"(a[3]), "r"(b[0]), "r"(b[1]));
}
DINLINE uint32_t pack_h2(float a, float b) {
    uint32_t r;
    asm("cvt.rn.f16x2.f32 %0, %1, %2;" : "=r"(r) : "f"(b), "f"(a));
    return r;
}

// ---- K1: all prep. Grid: [0,PA2) act (2 elems/thr); [PA2,PA2+8) baseW; then 128 splineW ----
__global__ void __launch_bounds__(256) k_prep(const float* __restrict__ x,
                                              const float* __restrict__ bw,
                                              const float* __restrict__ sw,
                                              int PA2) {
    __shared__ float tile[32][33];
    const int b = blockIdx.x, t = threadIdx.x;
    if (b < PA2) {
        int idx2 = b * 256 + t;                 // 2-element chunk id
        int n = idx2 >> 6, c2 = idx2 & 63;
        float2 x0 = *(const float2*)(x + n * 128 + c2 * 2);
        float xv[2] = {x0.x, x0.y};
        float v[5][2];
        uint32_t cfb[2];
        const float s6 = 0.16666666666666666f;
#pragma unroll
        for (int e = 0; e < 2; ++e) {
            float xe = xv[e];
            v[0][e] = xe / (1.0f + __expf(-xe));
            float xn = fminf(fmaxf(xe, -1.0f), 1.0f);
            float tt = (xn + 2.2f) * 2.5f;
            float fl = floorf(tt);
            float u  = tt - fl;
            int ii = (int)fl; ii = ii < 3 ? 3 : (ii > 7 ? 7 : ii);
            float u2 = u * u;
            v[1][e] = s6 * (1.0f + u * (-3.0f + u * (3.0f - u)));
            v[2][e] = s6 * (4.0f + u2 * (3.0f * u - 6.0f));
            v[3][e] = s6 * (1.0f + u * (3.0f + u * (3.0f - 3.0f * u)));
            v[4][e] = s6 * (u2 * u);
            cfb[e] = (uint32_t)(ii - 3);
        }
#pragma unroll
        for (int s = 0; s < 5; ++s)
            *(uint32_t*)&g_Ah[s][n][c2 * 2] = pack_h2(v[s][0], v[s][1]);
        // planar [n][jp][q]: i = c2*2 + e; jp = c2>>4, q = (c2&15)*2 + e (consecutive)
        *(unsigned short*)(g_cflp + n * 128 + (c2 >> 4) * 32 + (c2 & 15) * 2) =
            (unsigned short)(cfb[0] | (cfb[1] << 8));
    } else if (b < PA2 + 8) {
        int f8 = (b - PA2) * 256 + t;
        int c = f8 >> 4, ch = f8 & 15;
        const float4* wp = (const float4*)(bw + c * 128 + ch * 8);
        float4 w0 = wp[0], w1 = wp[1];
        uint4 hv;
        hv.x = pack_h2(w0.x, w0.y);
        hv.y = pack_h2(w0.z, w0.w);
        hv.z = pack_h2(w1.x, w1.y);
        hv.w = pack_h2(w1.z, w1.w);
        *(uint4*)&g_Wh[c][ch * 8] = hv;
    } else {
        int bb = b - PA2 - 8;
        int bc = bb >> 2, bi = bb & 3;
        int tx = t & 31, ty = t >> 5;
#pragma unroll
        for (int iy = 0; iy < 4; ++iy) {
            int il = ty + 8 * iy;
            tile[il][tx] = sw[(bi * 32 + il) * 1024 + bc * 32 + tx];
        }
        __syncthreads();
        {
            int cl = t >> 3, ch = t & 7;
            uint2 hv;
            hv.x = pack_h2(tile[ch * 4 + 0][cl], tile[ch * 4 + 1][cl]);
            hv.y = pack_h2(tile[ch * 4 + 2][cl], tile[ch * 4 + 3][cl]);
            int c = 128 + bc * 32 + cl, i = bi * 32 + ch * 4;
            *(uint2*)&g_Wh[c][i] = hv;
        }
    }
}

// ---- K2: fp16 HMMA GEMM, 4-stage k pipeline. grid (M/128, 9), 256 thr ----
// smem: A 128x256B @0 (32KB), W 128x256B @32768 (32KB).
DINLINE void gemm_pass(uint32_t sb, int ks0, int ks1,
                       int a_lrow, int a_lsel, int b_lrow0, int b_lsel,
                       float (&acc)[4][4][4]) {
#pragma unroll
    for (int ks = ks0; ks < ks1; ++ks) {
        uint32_t af[4][4];
#pragma unroll
        for (int mt = 0; mt < 4; ++mt) {
            int row = a_lrow + mt * 16;
            int q = ks * 2 + a_lsel;
            uint32_t addr = sb + row * 256 + (((q & 8) | ((q ^ row) & 7)) * 16);
            ldsm_x4(af[mt][0], af[mt][1], af[mt][2], af[mt][3], addr);
        }
        uint32_t bf[4][2];
#pragma unroll
        for (int h = 0; h < 2; ++h) {
            int row = b_lrow0 + h * 16;
            int q = ks * 2 + b_lsel;
            uint32_t addr = sb + 32768 + row * 256 + (((q & 8) | ((q ^ row) & 7)) * 16);
            uint32_t r0, r1, r2, r3;
            ldsm_x4(r0, r1, r2, r3, addr);
            bf[h * 2][0] = r0;     bf[h * 2][1] = r1;
            bf[h * 2 + 1][0] = r2; bf[h * 2 + 1][1] = r3;
        }
#pragma unroll
        for (int mt = 0; mt < 4; ++mt)
#pragma unroll
            for (int nt = 0; nt < 4; ++nt)
                mma16816(acc[mt][nt], af[mt], bf[nt]);
    }
}

__global__ void __launch_bounds__(256) k_gemm_mma(float* __restrict__ out) {
    extern __shared__ __align__(128) char smem[];
    const uint32_t sb = smem_u32(smem);
    const int tid = threadIdx.x, lane = tid & 31, wid = tid >> 5;
    const int m0 = blockIdx.x * 128, ct = blockIdx.y;
    const int sel = (ct == 0) ? 0 : 1 + ((ct - 1) >> 1);

    const __half* Asrc = &g_Ah[sel][m0][0];
    // 4 staging groups; group g covers chunks q = g*4 .. g*4+3 of A and W
#pragma unroll
    for (int g = 0; g < 4; ++g) {
#pragma unroll
        for (int it = 0; it < 2; ++it) {
            int idx = it * 256 + tid;
            int row = idx >> 2, q = g * 4 + (idx & 3);
            cp16(sb + row * 256 + (((q & 8) | ((q ^ row) & 7)) * 16), Asrc + row * 128 + q * 8);
        }
#pragma unroll
        for (int it = 0; it < 2; ++it) {
            int idx = it * 256 + tid;
            int row = idx >> 2, q = g * 4 + (idx & 3);
            cp16(sb + 32768 + row * 256 + (((q & 8) | ((q ^ row) & 7)) * 16),
                 &g_Wh[ct * 128 + row][q * 8]);
        }
        cp_commit();
    }

    const int wm = wid >> 2, wn = wid & 3;     // warp tile 64x32
    float acc[4][4][4];
#pragma unroll
    for (int i = 0; i < 4; ++i)
#pragma unroll
        for (int j = 0; j < 4; ++j)
#pragma unroll
            for (int k = 0; k < 4; ++k) acc[i][j][k] = 0.0f;

    const int a_lrow = wm * 64 + (lane & 15);
    const int a_lsel = lane >> 4;
    const int b_lrow0 = wn * 32 + ((lane >> 4) << 3) + (lane & 7);
    const int b_lsel = (lane >> 3) & 1;

    cp_wait<3>();
    __syncthreads();
    gemm_pass(sb, 0, 2, a_lrow, a_lsel, b_lrow0, b_lsel, acc);   // k 0..31
    cp_wait<2>();
    __syncthreads();
    gemm_pass(sb, 2, 4, a_lrow, a_lsel, b_lrow0, b_lsel, acc);   // k 32..63
    cp_wait<1>();
    __syncthreads();
    gemm_pass(sb, 4, 6, a_lrow, a_lsel, b_lrow0, b_lsel, acc);   // k 64..95
    cp_wait<0>();
    __syncthreads();
    gemm_pass(sb, 6, 8, a_lrow, a_lsel, b_lrow0, b_lsel, acc);   // k 96..127

    const int er = lane >> 2, ec = (lane & 3) * 2;
    if (ct == 0) {
#pragma unroll
        for (int mt = 0; mt < 4; ++mt)
#pragma unroll
            for (int nt = 0; nt < 4; ++nt) {
                int row = m0 + wm * 64 + mt * 16 + er;
                int col = wn * 32 + nt * 8 + ec;
                *(float2*)&out[row * 128 + col]       = make_float2(acc[mt][nt][0], acc[mt][nt][1]);
                *(float2*)&out[(row + 8) * 128 + col] = make_float2(acc[mt][nt][2], acc[mt][nt][3]);
            }
    } else {
#pragma unroll
        for (int mt = 0; mt < 4; ++mt)
#pragma unroll
            for (int nt = 0; nt < 4; ++nt) {
                int row = m0 + wm * 64 + mt * 16 + er;
                int col = (ct - 1) * 128 + wn * 32 + nt * 8 + ec;
                *(float2*)&g_Cs[row * 1024 + col]       = make_float2(acc[mt][nt][0], acc[mt][nt][1]);
                *(float2*)&g_Cs[(row + 8) * 1024 + col] = make_float2(acc[mt][nt][2], acc[mt][nt][3]);
            }
    }
}

// ---- K3: finalize ----
__global__ void __launch_bounds__(256) k_final(float* __restrict__ out) {
    int idx = blockIdx.x * 256 + threadIdx.x;
    int n = idx >> 7, o = idx & 127;
    int q = o >> 2, r2 = o & 3;
    float acc = out[idx];
    const unsigned char* cf = g_cflp + n * 128 + q;
    const float* Cs = g_Cs + n * 1024 + q * 8 + r2;
    float t0 = Cs[cf[0]];
    float t1 = Cs[256 + cf[32]];
    float t2 = Cs[512 + cf[64]];
    float t3 = Cs[768 + cf[96]];
    out[idx] = acc + (t0 + t1) + (t2 + t3);
}

extern "C" void kernel_launch(void* const* d_in, const int* in_sizes, int n_in,
                              void* d_out, int out_size) {
    const float* x  = (const float*)d_in[0];
    const float* bw = (const float*)d_in[1];
    const float* sw = (const float*)d_in[2];
    float* out = (float*)d_out;
    int N = in_sizes[0] / FIN;
    if (N > MAXN) N = MAXN;

    const int smem = 32768 + 32768;  // 64 KB
    cudaFuncSetAttribute(k_gemm_mma, cudaFuncAttributeMaxDynamicSharedMemorySize, smem);

    int PA2 = (N * FIN) / 512;       // activation blocks (2 elems/thread)
    k_prep<<<PA2 + 8 + 128, 256>>>(x, bw, sw, PA2);
    dim3 grid(N / 128, 9);
    k_gemm_mma<<<grid, 256, smem>>>(out);
    k_final<<<(N * FIN) / 256, 256>>>(out);
}

// round 14
// speedup vs baseline: 2.1053x; 1.0201x over previous
#include <cuda_runtime.h>
#include <cuda_fp16.h>
#include <cstdint>

#define DINLINE __device__ __forceinline__

static constexpr int MAXN = 2048;
static constexpr int FIN  = 128;

// ---- scratch (device globals; no allocation allowed) ----
__device__ __align__(16) __half g_Ah[5][MAXN][128];   // [sel][n][i] fp16
__device__ __align__(16) __half g_Wh[1152][128];      // [c][k] fp16, N-major
__device__ __align__(16) __half g_Csh[MAXN * 1024];   // spline GEMM out [n][1024], fp16
__device__ unsigned char g_cflp[MAXN * FIN];          // planar [n][jp][q]

// ---------------- PTX helpers ----------------
DINLINE uint32_t smem_u32(const void* p) {
    uint32_t a;
    asm("{ .reg .u64 t; cvta.to.shared.u64 t, %1; cvt.u32.u64 %0, t; }" : "=r"(a) : "l"(p));
    return a;
}
DINLINE void cp16(uint32_t s, const void* g) {
    asm volatile("cp.async.cg.shared.global [%0], [%1], 16;" :: "r"(s), "l"(g));
}
DINLINE void cp_commit() { asm volatile("cp.async.commit_group;"); }
template <int N_> DINLINE void cp_wait() {
    asm volatile("cp.async.wait_group %0;" :: "n"(N_));
}
DINLINE void ldsm_x4(uint32_t& r0, uint32_t& r1, uint32_t& r2, uint32_t& r3, uint32_t addr) {
    asm volatile("ldmatrix.sync.aligned.m8n8.x4.shared.b16 {%0,%1,%2,%3}, [%4];"
                 : "=r"(r0), "=r"(r1), "=r"(r2), "=r"(r3) : "r"(addr));
}
DINLINE void mma16816(float* d, const uint32_t* a, const uint32_t* b) {
    asm volatile(
        "mma.sync.aligned.m16n8k16.row.col.f32.f16.f16.f32 "
        "{%0,%1,%2,%3}, {%4,%5,%6,%7}, {%8,%9}, {%0,%1,%2,%3};"
        : "+f"(d[0]), "+f"(d[1]), "+f"(d[2]), "+f"(d[3])
        : "r"(a[0]), "r"(a[1]), "r"(a[2]), "r"(a[3]), "r"(b[0]), "r"(b[1]));
}
DINLINE uint32_t pack_h2(float a, float b) {
    uint32_t r;
    asm("cvt.rn.f16x2.f32 %0, %1, %2;" : "=r"(r) : "f"(b), "f"(a));
    return r;
}

// ---- K1: all prep (R13). Grid: [0,PA2) act (2 elems/thr); [PA2,PA2+8) baseW; then 128 splineW ----
__global__ void __launch_bounds__(256) k_prep(const float* __restrict__ x,
                                              const float* __restrict__ bw,
                                              const float* __restrict__ sw,
                                              int PA2) {
    __shared__ float tile[32][33];
    const int b = blockIdx.x, t = threadIdx.x;
    if (b < PA2) {
        int idx2 = b * 256 + t;
        int n = idx2 >> 6, c2 = idx2 & 63;
        float2 x0 = *(const float2*)(x + n * 128 + c2 * 2);
        float xv[2] = {x0.x, x0.y};
        float v[5][2];
        uint32_t cfb[2];
        const float s6 = 0.16666666666666666f;
#pragma unroll
        for (int e = 0; e < 2; ++e) {
            float xe = xv[e];
            v[0][e] = xe / (1.0f + __expf(-xe));
            float xn = fminf(fmaxf(xe, -1.0f), 1.0f);
            float tt = (xn + 2.2f) * 2.5f;
            float fl = floorf(tt);
            float u  = tt - fl;
            int ii = (int)fl; ii = ii < 3 ? 3 : (ii > 7 ? 7 : ii);
            float u2 = u * u;
            v[1][e] = s6 * (1.0f + u * (-3.0f + u * (3.0f - u)));
            v[2][e] = s6 * (4.0f + u2 * (3.0f * u - 6.0f));
            v[3][e] = s6 * (1.0f + u * (3.0f + u * (3.0f - 3.0f * u)));
            v[4][e] = s6 * (u2 * u);
            cfb[e] = (uint32_t)(ii - 3);
        }
#pragma unroll
        for (int s = 0; s < 5; ++s)
            *(uint32_t*)&g_Ah[s][n][c2 * 2] = pack_h2(v[s][0], v[s][1]);
        *(unsigned short*)(g_cflp + n * 128 + (c2 >> 4) * 32 + (c2 & 15) * 2) =
            (unsigned short)(cfb[0] | (cfb[1] << 8));
    } else if (b < PA2 + 8) {
        int f8 = (b - PA2) * 256 + t;
        int c = f8 >> 4, ch = f8 & 15;
        const float4* wp = (const float4*)(bw + c * 128 + ch * 8);
        float4 w0 = wp[0], w1 = wp[1];
        uint4 hv;
        hv.x = pack_h2(w0.x, w0.y);
        hv.y = pack_h2(w0.z, w0.w);
        hv.z = pack_h2(w1.x, w1.y);
        hv.w = pack_h2(w1.z, w1.w);
        *(uint4*)&g_Wh[c][ch * 8] = hv;
    } else {
        int bb = b - PA2 - 8;
        int bc = bb >> 2, bi = bb & 3;
        int tx = t & 31, ty = t >> 5;
#pragma unroll
        for (int iy = 0; iy < 4; ++iy) {
            int il = ty + 8 * iy;
            tile[il][tx] = sw[(bi * 32 + il) * 1024 + bc * 32 + tx];
        }
        __syncthreads();
        {
            int cl = t >> 3, ch = t & 7;
            uint2 hv;
            hv.x = pack_h2(tile[ch * 4 + 0][cl], tile[ch * 4 + 1][cl]);
            hv.y = pack_h2(tile[ch * 4 + 2][cl], tile[ch * 4 + 3][cl]);
            int c = 128 + bc * 32 + cl, i = bi * 32 + ch * 4;
            *(uint2*)&g_Wh[c][i] = hv;
        }
    }
}

// ---- K2: fp16 HMMA GEMM, 512 threads (16 warps), 4-stage k pipeline. grid (M/128, 9) ----
// smem: A 128x256B @0 (32KB), W 128x256B @32768 (32KB). Warp tile 32x32.
DINLINE void gemm_pass(uint32_t sb, int ks0, int ks1,
                       int a_lrow, int a_lsel, int b_lrow0, int b_lsel,
                       float (&acc)[2][4][4]) {
#pragma unroll
    for (int ks = ks0; ks < ks1; ++ks) {
        uint32_t af[2][4];
#pragma unroll
        for (int mt = 0; mt < 2; ++mt) {
            int row = a_lrow + mt * 16;
            int q = ks * 2 + a_lsel;
            uint32_t addr = sb + row * 256 + (((q & 8) | ((q ^ row) & 7)) * 16);
            ldsm_x4(af[mt][0], af[mt][1], af[mt][2], af[mt][3], addr);
        }
        uint32_t bf[4][2];
#pragma unroll
        for (int h = 0; h < 2; ++h) {
            int row = b_lrow0 + h * 16;
            int q = ks * 2 + b_lsel;
            uint32_t addr = sb + 32768 + row * 256 + (((q & 8) | ((q ^ row) & 7)) * 16);
            uint32_t r0, r1, r2, r3;
            ldsm_x4(r0, r1, r2, r3, addr);
            bf[h * 2][0] = r0;     bf[h * 2][1] = r1;
            bf[h * 2 + 1][0] = r2; bf[h * 2 + 1][1] = r3;
        }
#pragma unroll
        for (int mt = 0; mt < 2; ++mt)
#pragma unroll
            for (int nt = 0; nt < 4; ++nt)
                mma16816(acc[mt][nt], af[mt], bf[nt]);
    }
}

__global__ void __launch_bounds__(512) k_gemm_mma(float* __restrict__ out) {
    extern __shared__ __align__(128) char smem[];
    const uint32_t sb = smem_u32(smem);
    const int tid = threadIdx.x, lane = tid & 31, wid = tid >> 5;
    const int m0 = blockIdx.x * 128, ct = blockIdx.y;
    const int sel = (ct == 0) ? 0 : 1 + ((ct - 1) >> 1);

    const __half* Asrc = &g_Ah[sel][m0][0];
    // 4 staging groups; group g covers chunks q = g*4..g*4+3 (1 cp.async per thread per tile)
#pragma unroll
    for (int g = 0; g < 4; ++g) {
        {
            int row = tid >> 2, q = g * 4 + (tid & 3);
            cp16(sb + row * 256 + (((q & 8) | ((q ^ row) & 7)) * 16), Asrc + row * 128 + q * 8);
            cp16(sb + 32768 + row * 256 + (((q & 8) | ((q ^ row) & 7)) * 16),
                 &g_Wh[ct * 128 + row][q * 8]);
        }
        cp_commit();
    }

    const int wm = wid >> 2, wn = wid & 3;     // warp tile 32x32 (16 warps)
    float acc[2][4][4];
#pragma unroll
    for (int i = 0; i < 2; ++i)
#pragma unroll
        for (int j = 0; j < 4; ++j)
#pragma unroll
            for (int k = 0; k < 4; ++k) acc[i][j][k] = 0.0f;

    const int a_lrow = wm * 32 + (lane & 15);
    const int a_lsel = lane >> 4;
    const int b_lrow0 = wn * 32 + ((lane >> 4) << 3) + (lane & 7);
    const int b_lsel = (lane >> 3) & 1;

    cp_wait<3>();
    __syncthreads();
    gemm_pass(sb, 0, 2, a_lrow, a_lsel, b_lrow0, b_lsel, acc);
    cp_wait<2>();
    __syncthreads();
    gemm_pass(sb, 2, 4, a_lrow, a_lsel, b_lrow0, b_lsel, acc);
    cp_wait<1>();
    __syncthreads();
    gemm_pass(sb, 4, 6, a_lrow, a_lsel, b_lrow0, b_lsel, acc);
    cp_wait<0>();
    __syncthreads();
    gemm_pass(sb, 6, 8, a_lrow, a_lsel, b_lrow0, b_lsel, acc);

    const int er = lane >> 2, ec = (lane & 3) * 2;
    if (ct == 0) {
#pragma unroll
        for (int mt = 0; mt < 2; ++mt)
#pragma unroll
            for (int nt = 0; nt < 4; ++nt) {
                int row = m0 + wm * 32 + mt * 16 + er;
                int col = wn * 32 + nt * 8 + ec;
                *(float2*)&out[row * 128 + col]       = make_float2(acc[mt][nt][0], acc[mt][nt][1]);
                *(float2*)&out[(row + 8) * 128 + col] = make_float2(acc[mt][nt][2], acc[mt][nt][3]);
            }
    } else {
#pragma unroll
        for (int mt = 0; mt < 2; ++mt)
#pragma unroll
            for (int nt = 0; nt < 4; ++nt) {
                int row = m0 + wm * 32 + mt * 16 + er;
                int col = (ct - 1) * 128 + wn * 32 + nt * 8 + ec;
                *(uint32_t*)&g_Csh[row * 1024 + col]       = pack_h2(acc[mt][nt][0], acc[mt][nt][1]);
                *(uint32_t*)&g_Csh[(row + 8) * 1024 + col] = pack_h2(acc[mt][nt][2], acc[mt][nt][3]);
            }
    }
}

// ---- K3: finalize (fp16 gathers) ----
__global__ void __launch_bounds__(256) k_final(float* __restrict__ out) {
    int idx = blockIdx.x * 256 + threadIdx.x;
    int n = idx >> 7, o = idx & 127;
    int q = o >> 2, r2 = o & 3;
    float acc = out[idx];
    const unsigned char* cf = g_cflp + n * 128 + q;
    const __half* Cs = g_Csh + n * 1024 + q * 8 + r2;
    float t0 = __half2float(Cs[cf[0]]);
    float t1 = __half2float(Cs[256 + cf[32]]);
    float t2 = __half2float(Cs[512 + cf[64]]);
    float t3 = __half2float(Cs[768 + cf[96]]);
    out[idx] = acc + (t0 + t1) + (t2 + t3);
}

extern "C" void kernel_launch(void* const* d_in, const int* in_sizes, int n_in,
                              void* d_out, int out_size) {
    const float* x  = (const float*)d_in[0];
    const float* bw = (const float*)d_in[1];
    const float* sw = (const float*)d_in[2];
    float* out = (float*)d_out;
    int N = in_sizes[0] / FIN;
    if (N > MAXN) N = MAXN;

    const int smem = 32768 + 32768;  // 64 KB
    cudaFuncSetAttribute(k_gemm_mma, cudaFuncAttributeMaxDynamicSharedMemorySize, smem);

    int PA2 = (N * FIN) / 512;
    k_prep<<<PA2 + 8 + 128, 256>>>(x, bw, sw, PA2);
    dim3 grid(N / 128, 9);
    k_gemm_mma<<<grid, 512, smem>>>(out);
    k_final<<<(N * FIN) / 256, 256>>>(out);
}